// round 2
// baseline (speedup 1.0000x reference)
#include <cuda_runtime.h>
#include <math.h>

#define BB 2
#define NN 2048
#define CC 64
#define NK 9
#define KC 576            // NK * CC
#define GG 5              // bin grid 5x5, cell = 0.2 > prune radius 0.171
#define NCELL 25

#define R2f     0.01f
#define DILf    0.05f
#define FULLM   0xffffffffu

// knorm = 315 / (64 * pi * R^9), R = 0.1
#define KNORMf ((float)(315.0 / (64.0 * 3.14159265358979323846 * 1e-9)))

// ---------------- scratch (static device globals) --------------------------
__device__ float  g_coef[BB * NN];
__device__ float  g_Wr[CC * KC];            // [o][k*64+c]
__device__ float  g_dcoefS[BB * NN * CC];   // SORTED: [b][slot][c]
__device__ float2 g_sPos[BB * NN];          // sorted positions
__device__ int    g_slotOf[BB * NN];        // orig j -> slot
__device__ int    g_cellCnt[BB * NCELL];
__device__ int    g_cellStart[BB * NCELL];  // batch-relative slot
__device__ float  g_field[BB * NN * KC];    // [b][i_orig][k*64+c]

__device__ __forceinline__ int cell_of(float x, float y) {
    int cx = (int)(x * (float)GG); cx = min(GG - 1, max(0, cx));
    int cy = (int)(y * (float)GG); cy = min(GG - 1, max(0, cy));
    return cy * GG + cx;
}

// ---------------- packed f32x2 FMA (FFMA2; PTX-only pattern) ---------------
__device__ __forceinline__ unsigned long long pk2(float lo, float hi) {
    unsigned long long r;
    asm("mov.b64 %0, {%1, %2};" : "=l"(r) : "f"(lo), "f"(hi));
    return r;
}
__device__ __forceinline__ void fma2(unsigned long long& d,
                                     unsigned long long a,
                                     unsigned long long b) {
    asm("fma.rn.f32x2 %0, %1, %2, %0;" : "+l"(d) : "l"(a), "l"(b));
}
__device__ __forceinline__ float lo32(unsigned long long v) {
    return __uint_as_float((unsigned)(v & 0xffffffffull));
}
__device__ __forceinline__ float hi32(unsigned long long v) {
    return __uint_as_float((unsigned)(v >> 32));
}

// ---------------- prep1: coef + weight reorder -----------------------------
__global__ void prep1_kernel(const float* __restrict__ locs,
                             const float* __restrict__ density,
                             const float* __restrict__ weight) {
    int idx = blockIdx.x * blockDim.x + threadIdx.x;
    if (idx < BB * NN) {
        float im  = locs[idx * 3 + 2];
        float den = density[idx];
        g_coef[idx] = 1.0f / (im * den);
    }
    if (idx < CC * CC * NK) {
        int o = idx / (CC * NK);
        int r = idx - o * (CC * NK);
        int c = r / NK;
        int k = r - c * NK;
        g_Wr[o * KC + k * CC + c] = weight[idx];
    }
}

// ---------------- binning: count -------------------------------------------
__global__ void count_kernel(const float* __restrict__ locs) {
    int b    = blockIdx.x / NCELL;
    int cell = blockIdx.x % NCELL;
    int lane = threadIdx.x;
    int cnt  = 0;
    for (int j0 = 0; j0 < NN; j0 += 32) {
        int j = j0 + lane;
        const float* lp = locs + (size_t)(b * NN + j) * 3;
        int c = cell_of(lp[0], lp[1]);
        cnt += __popc(__ballot_sync(FULLM, c == cell));
    }
    if (lane == 0) g_cellCnt[blockIdx.x] = cnt;
}

// ---------------- binning: scan + ordered scatter (deterministic) ----------
__global__ void scatter_kernel(const float* __restrict__ locs) {
    int b    = blockIdx.x / NCELL;
    int cell = blockIdx.x % NCELL;
    int lane = threadIdx.x;

    int v = (lane < cell) ? g_cellCnt[b * NCELL + lane] : 0;
    #pragma unroll
    for (int o = 16; o; o >>= 1) v += __shfl_xor_sync(FULLM, v, o);
    int off = v;                    // exclusive prefix = batch-relative start
    if (lane == 0) g_cellStart[blockIdx.x] = off;

    for (int j0 = 0; j0 < NN; j0 += 32) {
        int j = j0 + lane;
        const float* lp = locs + (size_t)(b * NN + j) * 3;
        float x = lp[0], y = lp[1];
        bool match = (cell_of(x, y) == cell);
        unsigned m = __ballot_sync(FULLM, match);
        int rank = __popc(m & ((1u << lane) - 1u));
        if (match) {
            int slot = off + rank;
            g_slotOf[b * NN + j] = slot;
            g_sPos[b * NN + slot] = make_float2(x, y);
        }
        off += __popc(m);
    }
}

// ---------------- prep2: transpose data -> SORTED dcoefS -------------------
__global__ void prep2_kernel(const float* __restrict__ data) {
    __shared__ float s[32][33];
    int jt = blockIdx.x;      // 0..63
    int ct = blockIdx.y;      // 0..1
    int b  = blockIdx.z;      // 0..1
    int tx = threadIdx.x, ty = threadIdx.y;

    int c = ct * 32 + ty;
    int j = jt * 32 + tx;
    s[ty][tx] = data[(b * CC + c) * NN + j];
    __syncthreads();

    int j2 = jt * 32 + ty;
    int c2 = ct * 32 + tx;
    int slot = g_slotOf[b * NN + j2];
    g_dcoefS[((size_t)(b * NN + slot)) * CC + c2] =
        s[tx][ty] * g_coef[b * NN + j2];
}

// ---------------- main: binned sparse SPH gather ---------------------------
__device__ __forceinline__ float wfun(float t) {
    t = fmaxf(t, 0.0f);
    return (t * t) * (t * KNORMf);
}

__global__ __launch_bounds__(256) void convsp_main_kernel(
        const float* __restrict__ locs) {
    __shared__ float2 posS[NN];

    int b  = blockIdx.x >> 8;            // 512 blocks: 256 per batch
    int i0 = (blockIdx.x & 255) * 8;
    int tid = threadIdx.x;

    const float2* sp = g_sPos + (size_t)b * NN;
    for (int t = tid; t < NN; t += 256) posS[t] = sp[t];
    __syncthreads();

    int warp = tid >> 5;
    int lane = tid & 31;
    int i = i0 + warp;

    float xi = __ldg(&locs[(size_t)(b * NN + i) * 3 + 0]);
    float yi = __ldg(&locs[(size_t)(b * NN + i) * 3 + 1]);

    int cx = min(GG - 1, max(0, (int)(xi * (float)GG)));
    int cy = min(GG - 1, max(0, (int)(yi * (float)GG)));
    int cx0 = max(0, cx - 1), cx1 = min(GG - 1, cx + 1);
    int cy0 = max(0, cy - 1), cy1 = min(GG - 1, cy + 1);

    float2 acc0 = make_float2(0.f, 0.f), acc1 = acc0, acc2 = acc0;
    float2 acc3 = acc0, acc4 = acc0, acc5 = acc0;
    float2 acc6 = acc0, acc7 = acc0, acc8 = acc0;

    const float2* dcS2 = reinterpret_cast<const float2*>(g_dcoefS)
                         + ((size_t)b * NN * 32) + lane;

    for (int yy = cy0; yy <= cy1; yy++) {
        for (int xx = cx0; xx <= cx1; xx++) {
            int cell = yy * GG + xx;
            int cs  = g_cellStart[b * NCELL + cell];
            int ce  = cs + g_cellCnt[b * NCELL + cell];
            for (int t = cs; t < ce; t += 32) {
                int slot = t + lane;
                bool valid = slot < ce;
                float2 pj = posS[valid ? slot : 0];
                float dx = xi - pj.x;
                float dy = yi - pj.y;
                if (!valid) { dx = 1e9f; dy = 1e9f; }

                float bxm = dx - DILf, bxp = dx + DILf;
                float bym = dy - DILf, byp = dy + DILf;
                float rx0 = R2f - bxm * bxm;
                float rx1 = R2f - dx * dx;
                float rx2 = R2f - bxp * bxp;
                float ay0 = bym * bym;
                float ay1 = dy * dy;
                float ay2 = byp * byp;

                float w0 = wfun(rx0 - ay0);
                float w1 = wfun(rx0 - ay1);
                float w2 = wfun(rx0 - ay2);
                float w3 = wfun(rx1 - ay0);
                float w4 = wfun(rx1 - ay1);
                float w5 = wfun(rx1 - ay2);
                float w6 = wfun(rx2 - ay0);
                float w7 = wfun(rx2 - ay1);
                float w8 = wfun(rx2 - ay2);

                const float2* tp = dcS2 + ((size_t)t << 5);

#define DRAIN_K(WV, ACC)                                                  \
                {                                                         \
                    unsigned m = __ballot_sync(FULLM, (WV) > 0.0f);       \
                    while (m) {                                           \
                        int src = __ffs((int)m) - 1;                      \
                        m &= m - 1;                                       \
                        float s = __shfl_sync(FULLM, (WV), src);          \
                        float2 dc = __ldg(tp + ((size_t)src << 5));       \
                        ACC.x = fmaf(s, dc.x, ACC.x);                     \
                        ACC.y = fmaf(s, dc.y, ACC.y);                     \
                    }                                                     \
                }

                DRAIN_K(w0, acc0)
                DRAIN_K(w1, acc1)
                DRAIN_K(w2, acc2)
                DRAIN_K(w3, acc3)
                DRAIN_K(w4, acc4)
                DRAIN_K(w5, acc5)
                DRAIN_K(w6, acc6)
                DRAIN_K(w7, acc7)
                DRAIN_K(w8, acc8)
#undef DRAIN_K
            }
        }
    }

    float* f = g_field + (size_t)(b * NN + i) * KC + 2 * lane;
    *reinterpret_cast<float2*>(f + 0 * CC) = acc0;
    *reinterpret_cast<float2*>(f + 1 * CC) = acc1;
    *reinterpret_cast<float2*>(f + 2 * CC) = acc2;
    *reinterpret_cast<float2*>(f + 3 * CC) = acc3;
    *reinterpret_cast<float2*>(f + 4 * CC) = acc4;
    *reinterpret_cast<float2*>(f + 5 * CC) = acc5;
    *reinterpret_cast<float2*>(f + 6 * CC) = acc6;
    *reinterpret_cast<float2*>(f + 7 * CC) = acc7;
    *reinterpret_cast<float2*>(f + 8 * CC) = acc8;
}

// ---------------- final GEMM: out = bias + Wr @ field (FFMA2) --------------
__global__ __launch_bounds__(256) void wgemm_kernel(
        const float* __restrict__ bias, float* __restrict__ out) {
    __shared__ float Ws[64][68];   // [kk][o]
    __shared__ float Fs[64][17];   // [kk][i], i-tile = 16

    int b  = blockIdx.x >> 7;          // 256 blocks: 128 i-tiles per batch
    int i0 = (blockIdx.x & 127) * 16;
    int tid = threadIdx.x;

    int oq = (tid & 15) * 4;
    int iq = tid >> 4;                 // 0..15

    unsigned long long a01 = 0ull, a23 = 0ull;

    for (int kc0 = 0; kc0 < KC; kc0 += 64) {
        #pragma unroll
        for (int s = 0; s < 16; s++) {
            int l = tid + s * 256;
            int o  = l >> 6;
            int kk = l & 63;
            Ws[kk][o] = g_Wr[o * KC + kc0 + kk];
        }
        #pragma unroll
        for (int s = 0; s < 4; s++) {
            int l = tid + s * 256;
            int ii = l >> 6;
            int kk = l & 63;
            Fs[kk][ii] = g_field[(size_t)(b * NN + i0 + ii) * KC + kc0 + kk];
        }
        __syncthreads();

        #pragma unroll
        for (int kk = 0; kk < 64; kk++) {
            ulonglong2 wv = *reinterpret_cast<const ulonglong2*>(&Ws[kk][oq]);
            float fv = Fs[kk][iq];
            unsigned long long ff = pk2(fv, fv);
            fma2(a01, wv.x, ff);
            fma2(a23, wv.y, ff);
        }
        __syncthreads();
    }

    size_t base = (size_t)(b * CC) * NN + i0 + iq;
    out[base + (size_t)(oq + 0) * NN] = bias[oq + 0] + lo32(a01);
    out[base + (size_t)(oq + 1) * NN] = bias[oq + 1] + hi32(a01);
    out[base + (size_t)(oq + 2) * NN] = bias[oq + 2] + lo32(a23);
    out[base + (size_t)(oq + 3) * NN] = bias[oq + 3] + hi32(a23);
}

// ---------------- launcher -------------------------------------------------
extern "C" void kernel_launch(void* const* d_in, const int* in_sizes, int n_in,
                              void* d_out, int out_size) {
    // Bind inputs by unique element counts:
    // locs 12288, data 262144, density 4096, weight 36864, bias 64.
    const float* locs = nullptr;
    const float* data = nullptr;
    const float* density = nullptr;
    const float* weight = nullptr;
    const float* bias = nullptr;
    for (int idx = 0; idx < n_in; idx++) {
        switch (in_sizes[idx]) {
            case 12288:  locs    = (const float*)d_in[idx]; break;
            case 262144: data    = (const float*)d_in[idx]; break;
            case 4096:   density = (const float*)d_in[idx]; break;
            case 36864:  weight  = (const float*)d_in[idx]; break;
            case 64:     bias    = (const float*)d_in[idx]; break;
            default: break;
        }
    }
    float* out = (float*)d_out;

    prep1_kernel<<<144, 256>>>(locs, density, weight);
    count_kernel<<<BB * NCELL, 32>>>(locs);
    scatter_kernel<<<BB * NCELL, 32>>>(locs);
    prep2_kernel<<<dim3(64, 2, 2), dim3(32, 32)>>>(data);
    convsp_main_kernel<<<512, 256>>>(locs);
    wgemm_kernel<<<256, 256>>>(bias, out);
}

// round 3
// speedup vs baseline: 1.5198x; 1.5198x over previous
#include <cuda_runtime.h>
#include <math.h>

#define BB 2
#define NN 2048
#define CC 64
#define NK 9
#define KC 576            // NK * CC
#define GG 5              // 5x5 bins, cell 0.2 > prune radius 0.171
#define NCELL 25

#define R2f     0.01f
#define DILf    0.05f
#define FULLM   0xffffffffu

// knorm = 315 / (64 * pi * R^9), R = 0.1
#define KNORMf ((float)(315.0 / (64.0 * 3.14159265358979323846 * 1e-9)))

// ---------------- scratch ---------------------------------------------------
__device__ float  g_coef[BB * NN];
__device__ float  g_Wr[CC * KC];            // [o][k*64+c]
__device__ float  g_dcoefS[BB * NN * CC];   // SORTED rows: [b][slot][c]
__device__ float2 g_sPos[BB * NN];          // sorted positions
__device__ int    g_slotOf[BB * NN];        // orig j -> slot
__device__ int    g_origOf[BB * NN];        // slot -> orig j
__device__ int    g_cellCnt[BB * NCELL];
__device__ int    g_cellStart[BB * NCELL];
__device__ float  g_field[BB * NN * KC];    // [b][i_orig][k*64+c]

__device__ __forceinline__ int cell_of(float x, float y) {
    int cx = (int)(x * (float)GG); cx = min(GG - 1, max(0, cx));
    int cy = (int)(y * (float)GG); cy = min(GG - 1, max(0, cy));
    return cy * GG + cx;
}

// ---------------- packed f32x2 helpers --------------------------------------
__device__ __forceinline__ unsigned long long pk2(float lo, float hi) {
    unsigned long long r;
    asm("mov.b64 %0, {%1, %2};" : "=l"(r) : "f"(lo), "f"(hi));
    return r;
}
__device__ __forceinline__ void fma2(unsigned long long& d,
                                     unsigned long long a,
                                     unsigned long long b) {
    asm("fma.rn.f32x2 %0, %1, %2, %0;" : "+l"(d) : "l"(a), "l"(b));
}
__device__ __forceinline__ float lo32(unsigned long long v) {
    return __uint_as_float((unsigned)(v & 0xffffffffull));
}
__device__ __forceinline__ float hi32(unsigned long long v) {
    return __uint_as_float((unsigned)(v >> 32));
}

// ---------------- prep1: coef + weight reorder ------------------------------
__global__ void prep1_kernel(const float* __restrict__ locs,
                             const float* __restrict__ density,
                             const float* __restrict__ weight) {
    int idx = blockIdx.x * blockDim.x + threadIdx.x;
    if (idx < BB * NN) {
        float im  = locs[idx * 3 + 2];
        float den = density[idx];
        g_coef[idx] = 1.0f / (im * den);
    }
    if (idx < CC * CC * NK) {
        int o = idx / (CC * NK);
        int r = idx - o * (CC * NK);
        int c = r / NK;
        int k = r - c * NK;
        g_Wr[o * KC + k * CC + c] = weight[idx];
    }
}

// ---------------- binning: count + scan + ordered scatter, 1 block/batch ----
__global__ __launch_bounds__(800) void bin_kernel(const float* __restrict__ locs) {
    __shared__ int s_cnt[NCELL];
    int b    = blockIdx.x;
    int tid  = threadIdx.x;
    int w    = tid >> 5;       // warp = cell
    int lane = tid & 31;

    if (w < NCELL) {
        int cnt = 0;
        for (int j0 = 0; j0 < NN; j0 += 32) {
            const float* lp = locs + (size_t)(b * NN + j0 + lane) * 3;
            int c = cell_of(lp[0], lp[1]);
            cnt += __popc(__ballot_sync(FULLM, c == w));
        }
        if (lane == 0) s_cnt[w] = cnt;
    }
    __syncthreads();
    if (w < NCELL) {
        int v = (lane < w) ? s_cnt[lane] : 0;     // lane<=23 here, in-bounds
        #pragma unroll
        for (int o = 16; o; o >>= 1) v += __shfl_xor_sync(FULLM, v, o);
        int off = v;                              // exclusive prefix
        if (lane == 0) {
            g_cellStart[b * NCELL + w] = off;
            g_cellCnt[b * NCELL + w]   = s_cnt[w];
        }
        for (int j0 = 0; j0 < NN; j0 += 32) {
            int j = j0 + lane;
            const float* lp = locs + (size_t)(b * NN + j) * 3;
            float x = lp[0], y = lp[1];
            bool match = (cell_of(x, y) == w);
            unsigned m = __ballot_sync(FULLM, match);
            int rank = __popc(m & ((1u << lane) - 1u));
            if (match) {
                int slot = off + rank;
                g_slotOf[b * NN + j]    = slot;
                g_origOf[b * NN + slot] = j;
                g_sPos[b * NN + slot]   = make_float2(x, y);
            }
            off += __popc(m);
        }
    }
}

// ---------------- prep2: transpose data -> SORTED dcoefS --------------------
__global__ void prep2_kernel(const float* __restrict__ data) {
    __shared__ float s[32][33];
    int jt = blockIdx.x;      // 0..63
    int ct = blockIdx.y;      // 0..1
    int b  = blockIdx.z;      // 0..1
    int tx = threadIdx.x, ty = threadIdx.y;

    int c = ct * 32 + ty;
    int j = jt * 32 + tx;
    s[ty][tx] = data[(b * CC + c) * NN + j];
    __syncthreads();

    int j2 = jt * 32 + ty;
    int c2 = ct * 32 + tx;
    int slot = g_slotOf[b * NN + j2];
    g_dcoefS[((size_t)(b * NN + slot)) * CC + c2] =
        s[tx][ty] * g_coef[b * NN + j2];
}

// ---------------- main: binned gather, compact-to-smem + FFMA2 drain --------
__device__ __forceinline__ float wfun(float t) {
    t = fmaxf(t, 0.0f);
    return (t * t) * (t * KNORMf);
}

#define ENT 10   // ulonglongs per entry: 9 dup'd w-pairs + slot

__global__ __launch_bounds__(256) void convsp_main_kernel() {
    __shared__ unsigned long long buf[8][32 * ENT];   // 20.5 KB

    int b    = blockIdx.x >> 8;           // 512 blocks: 256 per batch
    int tid  = threadIdx.x;
    int warp = tid >> 5;
    int lane = tid & 31;

    int i_slot = (blockIdx.x & 255) * 8 + warp;       // SORTED order
    const float2* sp = g_sPos + (size_t)b * NN;

    float2 pi = __ldg(&sp[i_slot]);
    float xi = pi.x, yi = pi.y;

    int cx = min(GG - 1, max(0, (int)(xi * (float)GG)));
    int cy = min(GG - 1, max(0, (int)(yi * (float)GG)));
    int cx0 = max(0, cx - 1), cx1 = min(GG - 1, cx + 1);
    int cy0 = max(0, cy - 1), cy1 = min(GG - 1, cy + 1);

    unsigned long long a0 = 0, a1 = 0, a2 = 0, a3 = 0, a4 = 0,
                       a5 = 0, a6 = 0, a7 = 0, a8 = 0;

    const unsigned long long* dcU =
        reinterpret_cast<const unsigned long long*>(g_dcoefS)
        + ((size_t)b * NN * 32) + lane;

    unsigned long long* wb = buf[warp];

    for (int yy = cy0; yy <= cy1; yy++) {
        int c0 = b * NCELL + yy * GG + cx0;
        int c1 = b * NCELL + yy * GG + cx1;
        int rs = __ldg(&g_cellStart[c0]);
        int re = __ldg(&g_cellStart[c1]) + __ldg(&g_cellCnt[c1]);

        for (int t = rs; t < re; t += 32) {
            // ---- Phase A: lane-parallel w-compute + compaction ----
            int slot = t + lane;
            float2 pj = __ldg(&sp[min(slot, NN - 1)]);
            float dx = xi - pj.x;
            float dy = yi - pj.y;
            if (slot >= re) dx = 1e9f;

            float bxm = dx - DILf, bxp = dx + DILf;
            float bym = dy - DILf, byp = dy + DILf;
            float rx0 = fmaf(-bxm, bxm, R2f);
            float rx1 = fmaf(-dx,  dx,  R2f);
            float rx2 = fmaf(-bxp, bxp, R2f);
            float ay0 = bym * bym;
            float ay1 = dy * dy;
            float ay2 = byp * byp;

            float w0 = wfun(rx0 - ay0);
            float w1 = wfun(rx0 - ay1);
            float w2 = wfun(rx0 - ay2);
            float w3 = wfun(rx1 - ay0);
            float w4 = wfun(rx1 - ay1);
            float w5 = wfun(rx1 - ay2);
            float w6 = wfun(rx2 - ay0);
            float w7 = wfun(rx2 - ay1);
            float w8 = wfun(rx2 - ay2);

            float ssum = ((w0 + w1) + (w2 + w3)) + ((w4 + w5) + (w6 + w7)) + w8;
            bool active = ssum > 0.0f;

            unsigned m = __ballot_sync(FULLM, active);
            int cnt = __popc(m);
            if (active) {
                int rank = __popc(m & ((1u << lane) - 1u));
                ulonglong2* e2 = reinterpret_cast<ulonglong2*>(wb + rank * ENT);
                e2[0] = make_ulonglong2(pk2(w0, w0), pk2(w1, w1));
                e2[1] = make_ulonglong2(pk2(w2, w2), pk2(w3, w3));
                e2[2] = make_ulonglong2(pk2(w4, w4), pk2(w5, w5));
                e2[3] = make_ulonglong2(pk2(w6, w6), pk2(w7, w7));
                e2[4] = make_ulonglong2(pk2(w8, w8),
                                        (unsigned long long)(unsigned)slot);
            }
            __syncwarp();

            // ---- Phase B: entry-serial, lanes over channels, FFMA2 ----
#define BODY(E)                                                               \
            {                                                                 \
                const ulonglong2* q =                                         \
                    reinterpret_cast<const ulonglong2*>(wb + (E) * ENT);      \
                ulonglong2 q0 = q[0], q1 = q[1], q2 = q[2],                   \
                           q3 = q[3], q4 = q[4];                              \
                int sl = (int)(unsigned)q4.y;                                 \
                unsigned long long dc = __ldg(&dcU[(size_t)sl << 5]);         \
                fma2(a0, q0.x, dc); fma2(a1, q0.y, dc);                       \
                fma2(a2, q1.x, dc); fma2(a3, q1.y, dc);                       \
                fma2(a4, q2.x, dc); fma2(a5, q2.y, dc);                       \
                fma2(a6, q3.x, dc); fma2(a7, q3.y, dc);                       \
                fma2(a8, q4.x, dc);                                           \
            }
            int e = 0;
            for (; e + 2 <= cnt; e += 2) { BODY(e) BODY(e + 1) }
            if (e < cnt) { BODY(e) }
#undef BODY
            __syncwarp();
        }
    }

    int orig = __ldg(&g_origOf[b * NN + i_slot]);
    unsigned long long* f = reinterpret_cast<unsigned long long*>(
        g_field + (size_t)(b * NN + orig) * KC + 2 * lane);
    f[0 * 32] = a0;  f[1 * 32] = a1;  f[2 * 32] = a2;
    f[3 * 32] = a3;  f[4 * 32] = a4;  f[5 * 32] = a5;
    f[6 * 32] = a6;  f[7 * 32] = a7;  f[8 * 32] = a8;
}

// ---------------- final GEMM: out = bias + Wr @ field (FFMA2) ---------------
__global__ __launch_bounds__(256) void wgemm_kernel(
        const float* __restrict__ bias, float* __restrict__ out) {
    __shared__ float Ws[64][68];   // [kk][o]
    __shared__ float Fs[64][17];   // [kk][i], i-tile = 16

    int b  = blockIdx.x >> 7;          // 256 blocks: 128 i-tiles per batch
    int i0 = (blockIdx.x & 127) * 16;
    int tid = threadIdx.x;

    int oq = (tid & 15) * 4;
    int iq = tid >> 4;                 // 0..15

    unsigned long long a01 = 0ull, a23 = 0ull;

    for (int kc0 = 0; kc0 < KC; kc0 += 64) {
        #pragma unroll
        for (int s = 0; s < 16; s++) {
            int l = tid + s * 256;
            int o  = l >> 6;
            int kk = l & 63;
            Ws[kk][o] = g_Wr[o * KC + kc0 + kk];
        }
        #pragma unroll
        for (int s = 0; s < 4; s++) {
            int l = tid + s * 256;
            int ii = l >> 6;
            int kk = l & 63;
            Fs[kk][ii] = g_field[(size_t)(b * NN + i0 + ii) * KC + kc0 + kk];
        }
        __syncthreads();

        #pragma unroll
        for (int kk = 0; kk < 64; kk++) {
            ulonglong2 wv = *reinterpret_cast<const ulonglong2*>(&Ws[kk][oq]);
            float fv = Fs[kk][iq];
            unsigned long long ff = pk2(fv, fv);
            fma2(a01, wv.x, ff);
            fma2(a23, wv.y, ff);
        }
        __syncthreads();
    }

    size_t base = (size_t)(b * CC) * NN + i0 + iq;
    out[base + (size_t)(oq + 0) * NN] = bias[oq + 0] + lo32(a01);
    out[base + (size_t)(oq + 1) * NN] = bias[oq + 1] + hi32(a01);
    out[base + (size_t)(oq + 2) * NN] = bias[oq + 2] + lo32(a23);
    out[base + (size_t)(oq + 3) * NN] = bias[oq + 3] + hi32(a23);
}

// ---------------- launcher --------------------------------------------------
extern "C" void kernel_launch(void* const* d_in, const int* in_sizes, int n_in,
                              void* d_out, int out_size) {
    // Bind inputs by unique element counts:
    // locs 12288, data 262144, density 4096, weight 36864, bias 64.
    const float* locs = nullptr;
    const float* data = nullptr;
    const float* density = nullptr;
    const float* weight = nullptr;
    const float* bias = nullptr;
    for (int idx = 0; idx < n_in; idx++) {
        switch (in_sizes[idx]) {
            case 12288:  locs    = (const float*)d_in[idx]; break;
            case 262144: data    = (const float*)d_in[idx]; break;
            case 4096:   density = (const float*)d_in[idx]; break;
            case 36864:  weight  = (const float*)d_in[idx]; break;
            case 64:     bias    = (const float*)d_in[idx]; break;
            default: break;
        }
    }
    float* out = (float*)d_out;

    prep1_kernel<<<144, 256>>>(locs, density, weight);
    bin_kernel<<<BB, 800>>>(locs);
    prep2_kernel<<<dim3(64, 2, 2), dim3(32, 32)>>>(data);
    convsp_main_kernel<<<512, 256>>>();
    wgemm_kernel<<<256, 256>>>(bias, out);
}

// round 4
// speedup vs baseline: 1.7762x; 1.1687x over previous
#include <cuda_runtime.h>
#include <math.h>

#define BB 2
#define NN 2048
#define CC 64
#define NK 9
#define KC 576            // NK * CC
#define GG 5              // 5x5 bins, cell 0.2 > prune radius 0.171
#define NCELL 25

#define R2f     0.01f
#define DILf    0.05f
#define FULLM   0xffffffffu

// knorm = 315 / (64 * pi * R^9), R = 0.1
#define KNORMf ((float)(315.0 / (64.0 * 3.14159265358979323846 * 1e-9)))

// ---------------- scratch ---------------------------------------------------
__device__ float  g_coef[BB * NN];
__device__ float  g_Wt[KC * CC];            // [kc][o]  (kc = k*64+c)
__device__ float  g_dcoefS[BB * NN * CC];   // SORTED rows: [b][slot][c]
__device__ float2 g_sPos[BB * NN + 32];     // sorted positions + sentinel pad
__device__ int    g_slotOf[BB * NN];        // orig j -> slot
__device__ int    g_origOf[BB * NN];        // slot -> orig j
__device__ int    g_cellCnt[BB * NCELL];
__device__ int    g_cellStart[BB * NCELL];

__device__ __forceinline__ int cell_of(float x, float y) {
    int cx = (int)(x * (float)GG); cx = min(GG - 1, max(0, cx));
    int cy = (int)(y * (float)GG); cy = min(GG - 1, max(0, cy));
    return cy * GG + cx;
}

// ---------------- packed f32x2 helpers --------------------------------------
__device__ __forceinline__ unsigned long long pk2(float lo, float hi) {
    unsigned long long r;
    asm("mov.b64 %0, {%1, %2};" : "=l"(r) : "f"(lo), "f"(hi));
    return r;
}
__device__ __forceinline__ void fma2(unsigned long long& d,
                                     unsigned long long a,
                                     unsigned long long b) {
    asm("fma.rn.f32x2 %0, %1, %2, %0;" : "+l"(d) : "l"(a), "l"(b));
}

// ---------------- prep1: coef + weight transpose + sentinel -----------------
__global__ void prep1_kernel(const float* __restrict__ locs,
                             const float* __restrict__ density,
                             const float* __restrict__ weight) {
    int idx = blockIdx.x * blockDim.x + threadIdx.x;
    if (idx < BB * NN) {
        float im  = locs[idx * 3 + 2];
        float den = density[idx];
        g_coef[idx] = 1.0f / (im * den);
    }
    if (idx < 32) g_sPos[BB * NN + idx] = make_float2(1e9f, 1e9f);
    if (idx < CC * CC * NK) {
        int o = idx / (CC * NK);
        int r = idx - o * (CC * NK);
        int c = r / NK;
        int k = r - c * NK;
        g_Wt[(k * CC + c) * CC + o] = weight[idx];
    }
}

// ---------------- binning: count + scan + ordered scatter, 1 block/batch ----
__global__ __launch_bounds__(800) void bin_kernel(const float* __restrict__ locs) {
    __shared__ int s_cnt[NCELL];
    int b    = blockIdx.x;
    int tid  = threadIdx.x;
    int w    = tid >> 5;       // warp = cell
    int lane = tid & 31;

    if (w < NCELL) {
        int cnt = 0;
        for (int j0 = 0; j0 < NN; j0 += 32) {
            const float* lp = locs + (size_t)(b * NN + j0 + lane) * 3;
            int c = cell_of(lp[0], lp[1]);
            cnt += __popc(__ballot_sync(FULLM, c == w));
        }
        if (lane == 0) s_cnt[w] = cnt;
    }
    __syncthreads();
    if (w < NCELL) {
        int v = (lane < w) ? s_cnt[lane] : 0;
        #pragma unroll
        for (int o = 16; o; o >>= 1) v += __shfl_xor_sync(FULLM, v, o);
        int off = v;                              // exclusive prefix
        if (lane == 0) {
            g_cellStart[b * NCELL + w] = off;
            g_cellCnt[b * NCELL + w]   = s_cnt[w];
        }
        for (int j0 = 0; j0 < NN; j0 += 32) {
            int j = j0 + lane;
            const float* lp = locs + (size_t)(b * NN + j) * 3;
            float x = lp[0], y = lp[1];
            bool match = (cell_of(x, y) == w);
            unsigned m = __ballot_sync(FULLM, match);
            int rank = __popc(m & ((1u << lane) - 1u));
            if (match) {
                int slot = off + rank;
                g_slotOf[b * NN + j]    = slot;
                g_origOf[b * NN + slot] = j;
                g_sPos[b * NN + slot]   = make_float2(x, y);
            }
            off += __popc(m);
        }
    }
}

// ---------------- prep2: transpose data -> SORTED dcoefS --------------------
__global__ void prep2_kernel(const float* __restrict__ data) {
    __shared__ float s[32][33];
    int jt = blockIdx.x;      // 0..63
    int ct = blockIdx.y;      // 0..1
    int b  = blockIdx.z;      // 0..1
    int tx = threadIdx.x, ty = threadIdx.y;

    int c = ct * 32 + ty;
    int j = jt * 32 + tx;
    s[ty][tx] = data[(b * CC + c) * NN + j];
    __syncthreads();

    int j2 = jt * 32 + ty;
    int c2 = ct * 32 + tx;
    int slot = g_slotOf[b * NN + j2];
    g_dcoefS[((size_t)(b * NN + slot)) * CC + c2] =
        s[tx][ty] * g_coef[b * NN + j2];
}

// ---------------- main: binned gather + fused output GEMV -------------------
__device__ __forceinline__ float wfun(float t) {
    t = fmaxf(t, 0.0f);
    return (t * t) * (t * KNORMf);
}

#define ENT 10   // ulonglongs per entry: 9 dup'd w-pairs + slot

__global__ __launch_bounds__(128) void convsp_main_kernel(
        const float* __restrict__ bias, float* __restrict__ out) {
    __shared__ unsigned long long buf[4][32 * ENT];   // 10.25 KB

    int b    = blockIdx.x >> 9;           // 1024 blocks: 512 per batch
    int tid  = threadIdx.x;
    int warp = tid >> 5;
    int lane = tid & 31;

    int i_slot = (blockIdx.x & 511) * 4 + warp;       // SORTED order
    const float2* sp = g_sPos + (size_t)b * NN;

    float2 pi = __ldg(&sp[i_slot]);
    float xi = pi.x, yi = pi.y;

    int cx = min(GG - 1, max(0, (int)(xi * (float)GG)));
    int cy = min(GG - 1, max(0, (int)(yi * (float)GG)));
    int cx0 = max(0, cx - 1), cx1 = min(GG - 1, cx + 1);
    int cy0 = max(0, cy - 1), cy1 = min(GG - 1, cy + 1);

    unsigned long long a0 = 0, a1 = 0, a2 = 0, a3 = 0, a4 = 0,
                       a5 = 0, a6 = 0, a7 = 0, a8 = 0;

    const unsigned long long* dcU =
        reinterpret_cast<const unsigned long long*>(g_dcoefS)
        + ((size_t)b * NN * 32) + lane;

    unsigned long long* wb = buf[warp];

    for (int yy = cy0; yy <= cy1; yy++) {
        int c0 = b * NCELL + yy * GG + cx0;
        int c1 = b * NCELL + yy * GG + cx1;
        int rs = __ldg(&g_cellStart[c0]);
        int re = __ldg(&g_cellStart[c1]) + __ldg(&g_cellCnt[c1]);

        for (int t = rs; t < re; t += 32) {
            // ---- Phase A: lane-parallel w-compute + compaction ----
            int slot = t + lane;
            float2 pj = __ldg(&sp[slot]);     // sentinel pad covers tail
            float dx = xi - pj.x;
            float dy = yi - pj.y;
            if (slot >= re) dx = 1e9f;

            float bxm = dx - DILf, bxp = dx + DILf;
            float bym = dy - DILf, byp = dy + DILf;
            float rx0 = fmaf(-bxm, bxm, R2f);
            float rx1 = fmaf(-dx,  dx,  R2f);
            float rx2 = fmaf(-bxp, bxp, R2f);
            float ay0 = bym * bym;
            float ay1 = dy * dy;
            float ay2 = byp * byp;

            float w0 = wfun(rx0 - ay0);
            float w1 = wfun(rx0 - ay1);
            float w2 = wfun(rx0 - ay2);
            float w3 = wfun(rx1 - ay0);
            float w4 = wfun(rx1 - ay1);
            float w5 = wfun(rx1 - ay2);
            float w6 = wfun(rx2 - ay0);
            float w7 = wfun(rx2 - ay1);
            float w8 = wfun(rx2 - ay2);

            float ssum = ((w0 + w1) + (w2 + w3)) + ((w4 + w5) + (w6 + w7)) + w8;
            bool active = ssum > 0.0f;

            unsigned m = __ballot_sync(FULLM, active);
            int cnt = __popc(m);
            if (active) {
                int rank = __popc(m & ((1u << lane) - 1u));
                ulonglong2* e2 = reinterpret_cast<ulonglong2*>(wb + rank * ENT);
                e2[0] = make_ulonglong2(pk2(w0, w0), pk2(w1, w1));
                e2[1] = make_ulonglong2(pk2(w2, w2), pk2(w3, w3));
                e2[2] = make_ulonglong2(pk2(w4, w4), pk2(w5, w5));
                e2[3] = make_ulonglong2(pk2(w6, w6), pk2(w7, w7));
                e2[4] = make_ulonglong2(pk2(w8, w8),
                                        (unsigned long long)(unsigned)slot);
            }
            __syncwarp();

            // ---- Phase B: entry-serial, lanes over channels, FFMA2 ----
#define BODY(E)                                                               \
            {                                                                 \
                const ulonglong2* q =                                         \
                    reinterpret_cast<const ulonglong2*>(wb + (E) * ENT);      \
                ulonglong2 q0 = q[0], q1 = q[1], q2 = q[2],                   \
                           q3 = q[3], q4 = q[4];                              \
                int sl = (int)(unsigned)q4.y;                                 \
                unsigned long long dc = __ldg(&dcU[(size_t)sl << 5]);         \
                fma2(a0, q0.x, dc); fma2(a1, q0.y, dc);                       \
                fma2(a2, q1.x, dc); fma2(a3, q1.y, dc);                       \
                fma2(a4, q2.x, dc); fma2(a5, q2.y, dc);                       \
                fma2(a6, q3.x, dc); fma2(a7, q3.y, dc);                       \
                fma2(a8, q4.x, dc);                                           \
            }
            int e = 0;
            for (; e + 2 <= cnt; e += 2) { BODY(e) BODY(e + 1) }
            if (e < cnt) { BODY(e) }
#undef BODY
            __syncwarp();
        }
    }

    // ---- deposit field vector (576 floats) into this warp's smem buf ----
    wb[0 * 32 + lane] = a0;  wb[1 * 32 + lane] = a1;  wb[2 * 32 + lane] = a2;
    wb[3 * 32 + lane] = a3;  wb[4 * 32 + lane] = a4;  wb[5 * 32 + lane] = a5;
    wb[6 * 32 + lane] = a6;  wb[7 * 32 + lane] = a7;  wb[8 * 32 + lane] = a8;
    __syncwarp();

    // ---- fused GEMV: res[o] = sum_kc Wt[kc][o] * fs[kc], lane = o-pair ----
    const float4* fq = reinterpret_cast<const float4*>(wb);
    const float2* wt = reinterpret_cast<const float2*>(g_Wt) + lane;
    float p00 = 0.f, p01 = 0.f, p10 = 0.f, p11 = 0.f;
    float p20 = 0.f, p21 = 0.f, p30 = 0.f, p31 = 0.f;

    #pragma unroll 2
    for (int q = 0; q < KC / 4; q++) {
        float4 f4 = fq[q];                       // LDS.128 broadcast
        float2 v0 = __ldg(&wt[(q * 4 + 0) * 32]);
        float2 v1 = __ldg(&wt[(q * 4 + 1) * 32]);
        float2 v2 = __ldg(&wt[(q * 4 + 2) * 32]);
        float2 v3 = __ldg(&wt[(q * 4 + 3) * 32]);
        p00 = fmaf(v0.x, f4.x, p00); p01 = fmaf(v0.y, f4.x, p01);
        p10 = fmaf(v1.x, f4.y, p10); p11 = fmaf(v1.y, f4.y, p11);
        p20 = fmaf(v2.x, f4.z, p20); p21 = fmaf(v2.y, f4.z, p21);
        p30 = fmaf(v3.x, f4.w, p30); p31 = fmaf(v3.y, f4.w, p31);
    }
    float r0 = (p00 + p10) + (p20 + p30);
    float r1 = (p01 + p11) + (p21 + p31);

    int orig = __ldg(&g_origOf[b * NN + i_slot]);
    float2 bv = *reinterpret_cast<const float2*>(&bias[2 * lane]);
    out[((size_t)b * CC + 2 * lane)     * NN + orig] = bv.x + r0;
    out[((size_t)b * CC + 2 * lane + 1) * NN + orig] = bv.y + r1;
}

// ---------------- launcher --------------------------------------------------
extern "C" void kernel_launch(void* const* d_in, const int* in_sizes, int n_in,
                              void* d_out, int out_size) {
    // Bind inputs by unique element counts:
    // locs 12288, data 262144, density 4096, weight 36864, bias 64.
    const float* locs = nullptr;
    const float* data = nullptr;
    const float* density = nullptr;
    const float* weight = nullptr;
    const float* bias = nullptr;
    for (int idx = 0; idx < n_in; idx++) {
        switch (in_sizes[idx]) {
            case 12288:  locs    = (const float*)d_in[idx]; break;
            case 262144: data    = (const float*)d_in[idx]; break;
            case 4096:   density = (const float*)d_in[idx]; break;
            case 36864:  weight  = (const float*)d_in[idx]; break;
            case 64:     bias    = (const float*)d_in[idx]; break;
            default: break;
        }
    }
    float* out = (float*)d_out;

    prep1_kernel<<<144, 256>>>(locs, density, weight);
    bin_kernel<<<BB, 800>>>(locs);
    prep2_kernel<<<dim3(64, 2, 2), dim3(32, 32)>>>(data);
    convsp_main_kernel<<<1024, 128>>>(bias, out);
}